// round 16
// baseline (speedup 1.0000x reference)
#include <cuda_runtime.h>
#include <cuda_fp16.h>
#include <math.h>
#include <stdint.h>

// ---------------- problem constants ----------------
#define BATCH 4
#define T_LEN 4096
#define DIM 1024
#define DI 2048            // d_inner
#define DSTATE 16
#define KCONV 4
#define NSCALES 3
#define ROWS_FULL (BATCH * T_LEN)          // 16384
#define LN_EPS 1e-5f
#define NSPLIT 8           // bssm K-split factor

// ---------------- scratch (__device__ globals; no allocation allowed) ------
__device__ __align__(16) float g_xz[ROWS_FULL * 2 * DI];        // (x_in | gate)
__device__ __align__(16) float g_xs[ROWS_FULL * DI / 2];        // downsampled input
__device__ __align__(16) float g_xc[ROWS_FULL * DI];            // conv+silu output
__device__ __align__(16) float g_bssm[NSPLIT * ROWS_FULL * DSTATE];
__device__ __align__(16) float g_ys0[ROWS_FULL * DI];
__device__ __align__(16) float g_ys1[(ROWS_FULL / 2) * DI];
__device__ __align__(16) float g_ys2[(ROWS_FULL / 4) * DI];
__device__ __align__(16) float g_fused[ROWS_FULL * DI];
__device__ __align__(16) uint32_t g_ctx[ROWS_FULL * DI / 2];    // half2 k-paired
__device__ __align__(16) uint32_t g_h[ROWS_FULL * (DI / 4)];    // half2 k-paired
__device__ __align__(16) uint32_t g_mmin[ROWS_FULL * DI / 2];   // half2 k-paired
__device__ __align__(16) float g_preln[ROWS_FULL * DIM];
// half2 (k-paired) weight copies: in_proj | cg_w1 | cg_w2 | out_proj
__device__ __align__(16) uint32_t g_wh[5242880];
__device__ float g_sw[NSCALES];

// ---------------- helpers ----------------
__device__ __forceinline__ float sigmoidf(float x) { return 1.f / (1.f + expf(-x)); }
__device__ __forceinline__ float siluf(float x)    { return x / (1.f + expf(-x)); }
__device__ __forceinline__ float softplusf(float x){ return x > 20.f ? x : log1pf(expf(x)); }

__device__ __forceinline__ uint32_t pack_h2(float lo, float hi) {
    __half2 h = __floats2half2_rn(lo, hi);
    return *(uint32_t*)&h;
}

__device__ __forceinline__ void mma_f16(float* c, const uint32_t* a, uint32_t b0, uint32_t b1) {
    asm volatile(
        "mma.sync.aligned.m16n8k16.row.col.f32.f16.f16.f32 "
        "{%0,%1,%2,%3}, {%4,%5,%6,%7}, {%8,%9}, {%0,%1,%2,%3};\n"
        : "+f"(c[0]), "+f"(c[1]), "+f"(c[2]), "+f"(c[3])
        : "r"(a[0]), "r"(a[1]), "r"(a[2]), "r"(a[3]), "r"(b0), "r"(b1));
}

// ---------------- softmax over 3 scale weights ----------------
__global__ void softmax3_kernel(const float* __restrict__ sw) {
    float a = sw[0], b = sw[1], c = sw[2];
    float m = fmaxf(a, fmaxf(b, c));
    float ea = expf(a - m), eb = expf(b - m), ec = expf(c - m);
    float inv = 1.f / (ea + eb + ec);
    g_sw[0] = ea * inv; g_sw[1] = eb * inv; g_sw[2] = ec * inv;
}

// ---------------- weight preconvert: W[K][N] f32 -> Wh2[K/2][N] half2 -------
__global__ void cvt_h2_kernel(const float* __restrict__ in, uint32_t* __restrict__ out,
                              int Kh, int N) {
    int i = blockIdx.x * blockDim.x + threadIdx.x;
    int total = Kh * N;
    if (i >= total) return;
    int p = i / N, n = i - p * N;
    float a = in[(size_t)(2 * p) * N + n];
    float b = in[(size_t)(2 * p + 1) * N + n];
    out[(size_t)p * N + n] = pack_h2(a, b);
}

// ---------------- FP16 tensor-core GEMM with fused epilogues ----------------
// C[M,N] = A[M,K] * Bh2[K/2][N](half2 k-paired), row-major.
// AHALF: A is uint32 half2 k-paired [M][K/2]; else f32 [M][K].
// CHALF: C written as uint32 half2 n-paired [M][N/2]; else f32.
// Tile 128x128, K-tile 32, 256 threads = 8 warps of 64(m)x32(n). fp32 accumulate.
// EPI: 0=store, 1=silu, 2=sigmoid(acc)*e1[row*N+col]*silu(e2[row*4096+col]),
//      3=acc + e1[row*N+col]
#define A_GRP 132   // u32 stride per (mi,kstep) fragment group (128 + 4 pad)
#define B_GRP 130   // u32 stride per ni group (2*64 + 2 pad)

template<int EPI, int AHALF, int CHALF>
__global__ __launch_bounds__(256)
void tgemm_kernel(const void* __restrict__ Ain, const uint32_t* __restrict__ Bh,
                  void* __restrict__ Cout, int M, int N, int K,
                  const float* __restrict__ e1, const float* __restrict__ e2) {
    __shared__ __align__(16) uint32_t Asm[16 * A_GRP];
    __shared__ __align__(16) uint32_t Bsm[16 * B_GRP];

    const float* Af = (const float*)Ain;
    const uint32_t* Ah = (const uint32_t*)Ain;
    float* Cf = (float*)Cout;
    uint32_t* Ch = (uint32_t*)Cout;

    const int tid  = threadIdx.x;
    const int warp = tid >> 5;
    const int lane = tid & 31;
    const int wm = warp >> 2;
    const int wn = warp & 3;
    const int g  = lane >> 2;
    const int tg = lane & 3;

    const int m0 = blockIdx.y * 128;
    const int n0 = blockIdx.x * 128;
    const int Kh2 = K >> 1;

    float acc[4][4][4];
#pragma unroll
    for (int i = 0; i < 4; i++)
#pragma unroll
        for (int j = 0; j < 4; j++)
#pragma unroll
            for (int q = 0; q < 4; q++) acc[i][j][q] = 0.f;

    float4 a_pre[4];
    uint4  ah_pre[2];
    uint4  b_pre[2];

    // preload tile 0
    if (!AHALF) {
#pragma unroll
        for (int it = 0; it < 4; it++) {
            int v = tid + it * 256;
            int r = v >> 3, c4 = (v & 7) * 4;
            a_pre[it] = *(const float4*)&Af[(size_t)(m0 + r) * K + c4];
        }
    } else {
#pragma unroll
        for (int it = 0; it < 2; it++) {
            int v = tid + it * 256;
            int r = v >> 2, cu4 = (v & 3) * 4;
            ah_pre[it] = *(const uint4*)&Ah[(size_t)(m0 + r) * Kh2 + cu4];
        }
    }
#pragma unroll
    for (int it = 0; it < 2; it++) {
        int v = tid + it * 256;
        int prow = v >> 5, n4 = (v & 31) * 4;
        b_pre[it] = *(const uint4*)&Bh[(size_t)prow * N + n0 + n4];
    }

    for (int k0 = 0; k0 < K; k0 += 32) {
        // ---- scatter prefetched tile into fragment-ready smem ----
        if (!AHALF) {
#pragma unroll
            for (int it = 0; it < 4; it++) {
                int v = tid + it * 256;
                int r = v >> 3, c4 = (v & 7) * 4;
                int mi = r >> 4, rr = r & 15;
                float va[4] = {a_pre[it].x, a_pre[it].y, a_pre[it].z, a_pre[it].w};
#pragma unroll
                for (int j = 0; j < 2; j++) {
                    int c = c4 + 2 * j;
                    int p = (c & 15) >> 1, kstep = c >> 4;
                    int ls = (rr & 7) * 4 + (p & 3);
                    int slot = (p >> 2) * 2 + (rr >> 3);
                    Asm[(mi * 2 + kstep) * A_GRP + ls * 4 + slot] = pack_h2(va[2 * j], va[2 * j + 1]);
                }
            }
        } else {
#pragma unroll
            for (int it = 0; it < 2; it++) {
                int v = tid + it * 256;
                int r = v >> 2, cu4 = (v & 3) * 4;
                int mi = r >> 4, rr = r & 15;
                uint32_t ua[4] = {ah_pre[it].x, ah_pre[it].y, ah_pre[it].z, ah_pre[it].w};
#pragma unroll
                for (int j = 0; j < 4; j++) {
                    int p = cu4 + j;
                    int kstep = p >> 3, pp = p & 7;
                    int ls = (rr & 7) * 4 + (pp & 3);
                    int slot = (pp >> 2) * 2 + (rr >> 3);
                    Asm[(mi * 2 + kstep) * A_GRP + ls * 4 + slot] = ua[j];
                }
            }
        }
#pragma unroll
        for (int it = 0; it < 2; it++) {
            int v = tid + it * 256;
            int prow = v >> 5, n4 = (v & 31) * 4;
            int pp = prow & 7, kstep = prow >> 3;
            uint32_t vb[4] = {b_pre[it].x, b_pre[it].y, b_pre[it].z, b_pre[it].w};
#pragma unroll
            for (int j = 0; j < 4; j++) {
                int nn = n4 + j;
                int ni = nn >> 3, cc = nn & 7;
                int ls = cc * 4 + (pp & 3);
                int slot = pp >> 2;
                Bsm[ni * B_GRP + kstep * 64 + ls * 2 + slot] = vb[j];
            }
        }
        __syncthreads();

        // ---- prefetch next tile ----
        if (k0 + 32 < K) {
            if (!AHALF) {
#pragma unroll
                for (int it = 0; it < 4; it++) {
                    int v = tid + it * 256;
                    int r = v >> 3, c4 = (v & 7) * 4;
                    a_pre[it] = *(const float4*)&Af[(size_t)(m0 + r) * K + (k0 + 32) + c4];
                }
            } else {
                int ku0 = (k0 + 32) >> 1;
#pragma unroll
                for (int it = 0; it < 2; it++) {
                    int v = tid + it * 256;
                    int r = v >> 2, cu4 = (v & 3) * 4;
                    ah_pre[it] = *(const uint4*)&Ah[(size_t)(m0 + r) * Kh2 + ku0 + cu4];
                }
            }
            int ph0 = (k0 + 32) >> 1;
#pragma unroll
            for (int it = 0; it < 2; it++) {
                int v = tid + it * 256;
                int prow = v >> 5, n4 = (v & 31) * 4;
                b_pre[it] = *(const uint4*)&Bh[(size_t)(ph0 + prow) * N + n0 + n4];
            }
        }

        // ---- compute ----
#pragma unroll
        for (int kstep = 0; kstep < 2; kstep++) {
            uint32_t bq[4][2];
#pragma unroll
            for (int nj = 0; nj < 4; nj++) {
                int ni_g = wn * 4 + nj;
                *(uint2*)bq[nj] = *(const uint2*)&Bsm[ni_g * B_GRP + kstep * 64 + lane * 2];
            }
            uint32_t af[4][4];
#pragma unroll
            for (int mi = 0; mi < 4; mi++) {
                int mi_g = wm * 4 + mi;
                *(uint4*)af[mi] = *(const uint4*)&Asm[(mi_g * 2 + kstep) * A_GRP + lane * 4];
            }
#pragma unroll
            for (int mi = 0; mi < 4; mi++)
#pragma unroll
                for (int nj = 0; nj < 4; nj++)
                    mma_f16(acc[mi][nj], af[mi], bq[nj][0], bq[nj][1]);
        }
        __syncthreads();
    }

    // ---- epilogue ----
#pragma unroll
    for (int mi = 0; mi < 4; mi++) {
#pragma unroll
        for (int ni = 0; ni < 4; ni++) {
            int r0 = m0 + wm * 64 + mi * 16 + g;
            int cb = n0 + wn * 32 + ni * 8 + tg * 2;
#pragma unroll
            for (int half = 0; half < 2; half++) {
                int row = r0 + half * 8;
                float v0 = acc[mi][ni][half * 2 + 0];
                float v1 = acc[mi][ni][half * 2 + 1];
                size_t idx = (size_t)row * N + cb;
                float o0, o1;
                if (EPI == 0) {
                    o0 = v0; o1 = v1;
                } else if (EPI == 1) {
                    o0 = siluf(v0); o1 = siluf(v1);
                } else if (EPI == 2) {
                    float g0 = e2[(size_t)row * (2 * DI) + cb];
                    float g1 = e2[(size_t)row * (2 * DI) + cb + 1];
                    o0 = e1[idx] * sigmoidf(v0) * siluf(g0);
                    o1 = e1[idx + 1] * sigmoidf(v1) * siluf(g1);
                } else {
                    o0 = v0 + e1[idx];
                    o1 = v1 + e1[idx + 1];
                }
                if (CHALF) {
                    Ch[(size_t)row * (N >> 1) + (cb >> 1)] = pack_h2(o0, o1);
                } else {
                    *(float2*)&Cf[idx] = make_float2(o0, o1);
                }
            }
        }
    }
}

// ---------------- downsample (mean pool over time), float4 ----------------
__global__ void downsample_kernel(const float* __restrict__ xz, float* __restrict__ xs,
                                  int Ts, int stride) {
    int idx = blockIdx.x * blockDim.x + threadIdx.x;
    int total = BATCH * Ts * (DI / 4);
    if (idx >= total) return;
    int c4 = (idx & (DI / 4 - 1)) * 4;
    int rt = idx / (DI / 4);
    int t = rt % Ts;
    int bb = rt / Ts;
    float4 acc = make_float4(0.f, 0.f, 0.f, 0.f);
    for (int r = 0; r < stride; r++) {
        float4 v = *(const float4*)&xz[(size_t)(bb * T_LEN + t * stride + r) * (2 * DI) + c4];
        acc.x += v.x; acc.y += v.y; acc.z += v.z; acc.w += v.w;
    }
    float inv = 1.f / (float)stride;
    acc.x *= inv; acc.y *= inv; acc.z *= inv; acc.w *= inv;
    *(float4*)&xs[(size_t)(bb * Ts + t) * DI + c4] = acc;
}

// ---------------- causal depthwise conv (K=4) + silu, float4 ----------------
__global__ void conv_silu_kernel(const float* __restrict__ x, int ld,
                                 const float* __restrict__ w, const float* __restrict__ b,
                                 float* __restrict__ xc, int Ts) {
    int idx = blockIdx.x * blockDim.x + threadIdx.x;
    int total = BATCH * Ts * (DI / 4);
    if (idx >= total) return;
    int c4 = (idx & (DI / 4 - 1)) * 4;
    int rt = idx / (DI / 4);
    int t = rt % Ts;
    int bb = rt / Ts;
    float4 w0 = *(const float4*)&w[(c4 + 0) * KCONV];
    float4 w1 = *(const float4*)&w[(c4 + 1) * KCONV];
    float4 w2 = *(const float4*)&w[(c4 + 2) * KCONV];
    float4 w3 = *(const float4*)&w[(c4 + 3) * KCONV];
    float4 acc = *(const float4*)&b[c4];
    const float wk[4][4] = {{w0.x, w0.y, w0.z, w0.w}, {w1.x, w1.y, w1.z, w1.w},
                            {w2.x, w2.y, w2.z, w2.w}, {w3.x, w3.y, w3.z, w3.w}};
#pragma unroll
    for (int k = 0; k < KCONV; k++) {
        int tt = t - (KCONV - 1) + k;
        if (tt >= 0) {
            float4 v = *(const float4*)&x[(size_t)(bb * Ts + tt) * ld + c4];
            acc.x = fmaf(wk[0][k], v.x, acc.x);
            acc.y = fmaf(wk[1][k], v.y, acc.y);
            acc.z = fmaf(wk[2][k], v.z, acc.z);
            acc.w = fmaf(wk[3][k], v.w, acc.w);
        }
    }
    acc.x = siluf(acc.x); acc.y = siluf(acc.y);
    acc.z = siluf(acc.z); acc.w = siluf(acc.w);
    *(float4*)&xc[(size_t)rt * DI + c4] = acc;
}

// ---------------- B_ssm partials, register-tiled 4x4, transposed smem -------
#define BSSM_ROWS 256
#define XT_P 257

__global__ __launch_bounds__(256)
void bssm_kernel(const float* __restrict__ xc, const float* __restrict__ xproj,
                 float* __restrict__ bssm_p, int rows) {
    __shared__ float xt[32 * XT_P];
    __shared__ __align__(16) float ws[32 * 16];
    const int tid = threadIdx.x;
    const int row0 = blockIdx.x * BSSM_ROWS;
    const int ks0 = blockIdx.y * (DI / NSPLIT);
    const int rg = tid >> 2;
    const int jq = tid & 3;
    float acc[4][4];
#pragma unroll
    for (int i = 0; i < 4; i++)
#pragma unroll
        for (int j = 0; j < 4; j++) acc[i][j] = 0.f;

    for (int k0 = ks0; k0 < ks0 + DI / NSPLIT; k0 += 32) {
#pragma unroll
        for (int i = 0; i < 8; i++) {
            int v = tid + i * 256;
            int lr = v >> 3, c4 = (v & 7) * 4;
            float4 xv = *(const float4*)&xc[(size_t)(row0 + lr) * DI + k0 + c4];
            xt[(c4 + 0) * XT_P + lr] = xv.x;
            xt[(c4 + 1) * XT_P + lr] = xv.y;
            xt[(c4 + 2) * XT_P + lr] = xv.z;
            xt[(c4 + 3) * XT_P + lr] = xv.w;
        }
        {
            int kk = tid >> 4, j = tid & 15;
#pragma unroll
            for (int i = 0; i < 2; i++)
                ws[(kk + i * 16) * 16 + j] = xproj[(size_t)(k0 + kk + i * 16) * (2 * DSTATE) + j];
        }
        __syncthreads();
#pragma unroll 8
        for (int kk = 0; kk < 32; kk++) {
            float4 w4 = *(const float4*)&ws[kk * 16 + jq * 4];
            float x0 = xt[kk * XT_P + rg * 4 + 0];
            float x1 = xt[kk * XT_P + rg * 4 + 1];
            float x2 = xt[kk * XT_P + rg * 4 + 2];
            float x3 = xt[kk * XT_P + rg * 4 + 3];
            acc[0][0] = fmaf(x0, w4.x, acc[0][0]); acc[0][1] = fmaf(x0, w4.y, acc[0][1]);
            acc[0][2] = fmaf(x0, w4.z, acc[0][2]); acc[0][3] = fmaf(x0, w4.w, acc[0][3]);
            acc[1][0] = fmaf(x1, w4.x, acc[1][0]); acc[1][1] = fmaf(x1, w4.y, acc[1][1]);
            acc[1][2] = fmaf(x1, w4.z, acc[1][2]); acc[1][3] = fmaf(x1, w4.w, acc[1][3]);
            acc[2][0] = fmaf(x2, w4.x, acc[2][0]); acc[2][1] = fmaf(x2, w4.y, acc[2][1]);
            acc[2][2] = fmaf(x2, w4.z, acc[2][2]); acc[2][3] = fmaf(x2, w4.w, acc[2][3]);
            acc[3][0] = fmaf(x3, w4.x, acc[3][0]); acc[3][1] = fmaf(x3, w4.y, acc[3][1]);
            acc[3][2] = fmaf(x3, w4.z, acc[3][2]); acc[3][3] = fmaf(x3, w4.w, acc[3][3]);
        }
        __syncthreads();
    }
#pragma unroll
    for (int i = 0; i < 4; i++) {
        size_t o = ((size_t)blockIdx.y * rows + row0 + rg * 4 + i) * DSTATE + jq * 4;
        *(float4*)&bssm_p[o] = *(float4*)acc[i];
    }
}

// ---------------- SSM pointwise: 8 rows/block, dtw slice in registers -------
__global__ __launch_bounds__(256)
void ssm_pw_kernel(const float* __restrict__ xc, const float* __restrict__ bssm_p,
                   const float* __restrict__ dtw, const float* __restrict__ dtb,
                   const float* __restrict__ D, const float* __restrict__ xs, int ld,
                   float* __restrict__ ys, int rows) {
    const int r0 = blockIdx.x * 8;
    const int c4 = blockIdx.y * 1024 + threadIdx.x * 4;

    float4 wv[DSTATE];
#pragma unroll
    for (int k = 0; k < DSTATE; k++)
        wv[k] = *(const float4*)&dtw[k * DI + c4];
    float4 dtb4 = *(const float4*)&dtb[c4];
    float4 D4   = *(const float4*)&D[c4];

    __shared__ float bs[8 * DSTATE];
    if (threadIdx.x < 8 * DSTATE) {
        int rr = threadIdx.x >> 4, k = threadIdx.x & 15;
        float v = 0.f;
#pragma unroll
        for (int sp = 0; sp < NSPLIT; sp++)
            v += bssm_p[((size_t)sp * rows + r0 + rr) * DSTATE + k];
        bs[rr * DSTATE + k] = v;
    }
    __syncthreads();

#pragma unroll
    for (int rr = 0; rr < 8; rr++) {
        int row = r0 + rr;
        float4 dt = dtb4;
#pragma unroll
        for (int k = 0; k < DSTATE; k++) {
            float bk = bs[rr * DSTATE + k];
            dt.x = fmaf(bk, wv[k].x, dt.x);
            dt.y = fmaf(bk, wv[k].y, dt.y);
            dt.z = fmaf(bk, wv[k].z, dt.z);
            dt.w = fmaf(bk, wv[k].w, dt.w);
        }
        float4 xcv = *(const float4*)&xc[(size_t)row * DI + c4];
        float4 xv  = *(const float4*)&xs[(size_t)row * ld + c4];
        float4 o;
        o.x = xcv.x * sigmoidf(softplusf(dt.x)) + D4.x * xv.x;
        o.y = xcv.y * sigmoidf(softplusf(dt.y)) + D4.y * xv.y;
        o.z = xcv.z * sigmoidf(softplusf(dt.z)) + D4.z * xv.z;
        o.w = xcv.w * sigmoidf(softplusf(dt.w)) + D4.w * xv.w;
        *(float4*)&ys[(size_t)row * DI + c4] = o;
    }
}

// ---------------- merged upsample + fuse; ctx stored half2 k-paired ---------
__global__ void ups_fuse_kernel(const float* __restrict__ ys0,
                                const float* __restrict__ ys1,
                                const float* __restrict__ ys2,
                                float* __restrict__ fused, uint32_t* __restrict__ ctx) {
    int idx = blockIdx.x * blockDim.x + threadIdx.x;
    const int total4 = ROWS_FULL * (DI / 4);
    if (idx >= total4) return;
    int c4 = (idx & (DI / 4 - 1)) * 4;
    int rt = idx / (DI / 4);
    int t = rt % T_LEN;
    int bb = rt / T_LEN;

    float4 v0 = *(const float4*)&ys0[(size_t)(bb * T_LEN + t) * DI + c4];

    float4 v1, v2;
    {
        const int Ts = T_LEN / 2;
        float coord = (t + 0.5f) * 0.5f - 0.5f;
        coord = fminf(fmaxf(coord, 0.f), (float)(Ts - 1));
        int lo = (int)floorf(coord);
        int hi = min(lo + 1, Ts - 1);
        float wf = coord - (float)lo;
        float4 a = *(const float4*)&ys1[(size_t)(bb * Ts + lo) * DI + c4];
        float4 b = *(const float4*)&ys1[(size_t)(bb * Ts + hi) * DI + c4];
        v1.x = a.x + (b.x - a.x) * wf; v1.y = a.y + (b.y - a.y) * wf;
        v1.z = a.z + (b.z - a.z) * wf; v1.w = a.w + (b.w - a.w) * wf;
    }
    {
        const int Ts = T_LEN / 4;
        float coord = (t + 0.5f) * 0.25f - 0.5f;
        coord = fminf(fmaxf(coord, 0.f), (float)(Ts - 1));
        int lo = (int)floorf(coord);
        int hi = min(lo + 1, Ts - 1);
        float wf = coord - (float)lo;
        float4 a = *(const float4*)&ys2[(size_t)(bb * Ts + lo) * DI + c4];
        float4 b = *(const float4*)&ys2[(size_t)(bb * Ts + hi) * DI + c4];
        v2.x = a.x + (b.x - a.x) * wf; v2.y = a.y + (b.y - a.y) * wf;
        v2.z = a.z + (b.z - a.z) * wf; v2.w = a.w + (b.w - a.w) * wf;
    }

    float w0 = g_sw[0], w1 = g_sw[1], w2 = g_sw[2];
    float4 f;
    f.x = w0 * v0.x + w1 * v1.x + w2 * v2.x;
    f.y = w0 * v0.y + w1 * v1.y + w2 * v2.y;
    f.z = w0 * v0.z + w1 * v1.z + w2 * v2.z;
    f.w = w0 * v0.w + w1 * v1.w + w2 * v2.w;
    const float third = 1.f / 3.f;
    float cx0 = (v0.x + v1.x + v2.x) * third;
    float cx1 = (v0.y + v1.y + v2.y) * third;
    float cx2 = (v0.z + v1.z + v2.z) * third;
    float cx3 = (v0.w + v1.w + v2.w) * third;

    size_t o = (size_t)rt * DI + c4;
    *(float4*)&fused[o] = f;
    uint2 cp;
    cp.x = pack_h2(cx0, cx1);
    cp.y = pack_h2(cx2, cx3);
    *(uint2*)&ctx[o >> 1] = cp;
}

// ---------------- LayerNorm over last dim (1024), float4 ----------------
__global__ __launch_bounds__(256)
void ln_kernel(const float* __restrict__ y, const float* __restrict__ g,
               const float* __restrict__ b, float* __restrict__ out) {
    int row = blockIdx.x;
    const float* yr = y + (size_t)row * DIM;
    int c4 = threadIdx.x * 4;
    float4 v = *(const float4*)&yr[c4];
    float s  = v.x + v.y + v.z + v.w;
    float s2 = v.x * v.x + v.y * v.y + v.z * v.z + v.w * v.w;
#pragma unroll
    for (int o = 16; o > 0; o >>= 1) {
        s  += __shfl_down_sync(0xffffffffu, s, o);
        s2 += __shfl_down_sync(0xffffffffu, s2, o);
    }
    __shared__ float shs[8], shs2[8];
    __shared__ float smu, srstd;
    int wid = threadIdx.x >> 5, lane = threadIdx.x & 31;
    if (lane == 0) { shs[wid] = s; shs2[wid] = s2; }
    __syncthreads();
    if (wid == 0) {
        s  = lane < 8 ? shs[lane]  : 0.f;
        s2 = lane < 8 ? shs2[lane] : 0.f;
#pragma unroll
        for (int o = 4; o > 0; o >>= 1) {
            s  += __shfl_down_sync(0xffffffffu, s, o);
            s2 += __shfl_down_sync(0xffffffffu, s2, o);
        }
        if (lane == 0) {
            float mu = s / DIM;
            float var = s2 / DIM - mu * mu;
            smu = mu;
            srstd = rsqrtf(var + LN_EPS);
        }
    }
    __syncthreads();
    float mu = smu, rstd = srstd;
    float4 gv = *(const float4*)&g[c4];
    float4 bv = *(const float4*)&b[c4];
    float4 o;
    o.x = (v.x - mu) * rstd * gv.x + bv.x;
    o.y = (v.y - mu) * rstd * gv.y + bv.y;
    o.z = (v.z - mu) * rstd * gv.z + bv.z;
    o.w = (v.w - mu) * rstd * gv.w + bv.w;
    *(float4*)&out[(size_t)row * DIM + c4] = o;
}

// ---------------- launch ----------------
extern "C" void kernel_launch(void* const* d_in, const int* in_sizes, int n_in,
                              void* d_out, int out_size) {
    const float* x        = (const float*)d_in[0];
    const float* in_proj  = (const float*)d_in[1];
    const float* conv_w   = (const float*)d_in[2];
    const float* conv_b   = (const float*)d_in[3];
    const float* xproj_w  = (const float*)d_in[4];
    const float* dtproj_w = (const float*)d_in[5];
    const float* dtproj_b = (const float*)d_in[6];
    const float* D_param  = (const float*)d_in[7];
    const float* scale_w  = (const float*)d_in[8];
    const float* cg_w1    = (const float*)d_in[9];
    const float* cg_w2    = (const float*)d_in[10];
    const float* out_proj = (const float*)d_in[11];
    const float* ln_g     = (const float*)d_in[12];
    const float* ln_b     = (const float*)d_in[13];
    float* out = (float*)d_out;

    float *p_xz, *p_xs, *p_xc, *p_bssm, *p_ys0, *p_ys1, *p_ys2, *p_fused, *p_preln;
    uint32_t *p_ctx, *p_h, *p_mmin, *p_wh;
    cudaGetSymbolAddress((void**)&p_xz, g_xz);
    cudaGetSymbolAddress((void**)&p_xs, g_xs);
    cudaGetSymbolAddress((void**)&p_xc, g_xc);
    cudaGetSymbolAddress((void**)&p_bssm, g_bssm);
    cudaGetSymbolAddress((void**)&p_ys0, g_ys0);
    cudaGetSymbolAddress((void**)&p_ys1, g_ys1);
    cudaGetSymbolAddress((void**)&p_ys2, g_ys2);
    cudaGetSymbolAddress((void**)&p_fused, g_fused);
    cudaGetSymbolAddress((void**)&p_ctx, g_ctx);
    cudaGetSymbolAddress((void**)&p_h, g_h);
    cudaGetSymbolAddress((void**)&p_mmin, g_mmin);
    cudaGetSymbolAddress((void**)&p_preln, g_preln);
    cudaGetSymbolAddress((void**)&p_wh, g_wh);

    uint32_t* p_w0h = p_wh;                                   // [512][4096]
    uint32_t* p_w1h = p_w0h + (size_t)(DIM / 2) * 2 * DI;     // [1024][1024]
    uint32_t* p_w2h = p_w1h + (size_t)(DI / 2) * (DI / 2);    // [512][2048]
    uint32_t* p_w3h = p_w2h + (size_t)(DI / 4) * DI;          // [1024][1024]

    softmax3_kernel<<<1, 1>>>(scale_w);

    // 0) preconvert weights to half2 (k-paired) layout
    {
        int n;
        n = (DIM / 2) * 2 * DI;
        cvt_h2_kernel<<<(n + 255) / 256, 256>>>(in_proj, p_w0h, DIM / 2, 2 * DI);
        n = (DI / 2) * (DI / 2);
        cvt_h2_kernel<<<(n + 255) / 256, 256>>>(cg_w1, p_w1h, DI / 2, DI / 2);
        n = (DI / 4) * DI;
        cvt_h2_kernel<<<(n + 255) / 256, 256>>>(cg_w2, p_w2h, DI / 4, DI);
        n = (DI / 2) * DIM;
        cvt_h2_kernel<<<(n + 255) / 256, 256>>>(out_proj, p_w3h, DI / 2, DIM);
    }

    // 1) xz = x @ in_proj_w   (16384 x 4096, K=1024), A f32, C f32
    {
        dim3 grid(2 * DI / 128, ROWS_FULL / 128);
        tgemm_kernel<0, 0, 0><<<grid, 256>>>(x, p_w0h, p_xz, ROWS_FULL, 2 * DI, DIM,
                                             nullptr, nullptr);
    }

    // 2) per-scale SSM path
    float* ys_bufs[NSCALES] = {p_ys0, p_ys1, p_ys2};
    for (int s = 0; s < NSCALES; s++) {
        int stride = 1 << s;
        int Ts = T_LEN / stride;
        int rows = BATCH * Ts;
        int total4 = rows * (DI / 4);
        const float* xin;
        int ld;
        if (s == 0) {
            xin = p_xz; ld = 2 * DI;
        } else {
            downsample_kernel<<<(total4 + 255) / 256, 256>>>(p_xz, p_xs, Ts, stride);
            xin = p_xs; ld = DI;
        }
        conv_silu_kernel<<<(total4 + 255) / 256, 256>>>(xin, ld,
                                                        conv_w + (size_t)s * DI * KCONV,
                                                        conv_b + (size_t)s * DI,
                                                        p_xc, Ts);
        {
            dim3 bgrid(rows / BSSM_ROWS, NSPLIT);
            bssm_kernel<<<bgrid, 256>>>(p_xc, xproj_w + (size_t)s * DI * 2 * DSTATE,
                                        p_bssm, rows);
        }
        {
            dim3 sgrid(rows / 8, DI / 1024);
            ssm_pw_kernel<<<sgrid, 256>>>(p_xc, p_bssm,
                                          dtproj_w + (size_t)s * DSTATE * DI,
                                          dtproj_b + (size_t)s * DI,
                                          D_param + (size_t)s * DI,
                                          xin, ld, ys_bufs[s], rows);
        }
    }

    // 2b) merged upsample + fuse (ctx stored half2)
    {
        int total4 = ROWS_FULL * (DI / 4);
        ups_fuse_kernel<<<(total4 + 255) / 256, 256>>>(p_ys0, p_ys1, p_ys2, p_fused, p_ctx);
    }

    // 3) h = silu(ctx @ cg_w1)   (A half, C half)
    {
        dim3 grid((DI / 2) / 128, ROWS_FULL / 128);
        tgemm_kernel<1, 1, 1><<<grid, 256>>>(p_ctx, p_w1h, p_h, ROWS_FULL, DI / 2, DI,
                                             nullptr, nullptr);
    }
    // 4) mm_in = fused * sigmoid(h @ cg_w2) * silu(gate)   (A half, C half)
    {
        dim3 grid(DI / 128, ROWS_FULL / 128);
        tgemm_kernel<2, 1, 1><<<grid, 256>>>(p_h, p_w2h, p_mmin, ROWS_FULL, DI, DI / 2,
                                             p_fused, p_xz + DI);
    }
    // 5) preln = mm_in @ out_proj + x   (A half, C f32)
    {
        dim3 grid(DIM / 128, ROWS_FULL / 128);
        tgemm_kernel<3, 1, 0><<<grid, 256>>>(p_mmin, p_w3h, p_preln, ROWS_FULL, DIM, DI,
                                             x, nullptr);
    }
    // 6) LayerNorm -> out
    ln_kernel<<<ROWS_FULL, 256>>>(p_preln, ln_g, ln_b, out);
}

// round 17
// speedup vs baseline: 1.0372x; 1.0372x over previous
#include <cuda_runtime.h>
#include <cuda_fp16.h>
#include <math.h>
#include <stdint.h>

// ---------------- problem constants ----------------
#define BATCH 4
#define T_LEN 4096
#define DIM 1024
#define DI 2048            // d_inner
#define DSTATE 16
#define KCONV 4
#define NSCALES 3
#define ROWS_FULL (BATCH * T_LEN)          // 16384
#define LN_EPS 1e-5f
#define NSPLIT 8           // bssm K-split factor

#define ROWS0 16384
#define ROWS1 8192
#define ROWS2 4096
#define ROWS_TOT (ROWS0 + ROWS1 + ROWS2)   // 28672
#define SB0 0
#define SB1 (NSPLIT * ROWS0 * DSTATE)              // 2097152
#define SB2 (SB1 + NSPLIT * ROWS1 * DSTATE)        // 3145728

// ---------------- scratch (__device__ globals; no allocation allowed) ------
__device__ __align__(16) float g_xz[ROWS_FULL * 2 * DI];        // (x_in | gate)
__device__ __align__(16) float g_xs1[ROWS1 * DI];
__device__ __align__(16) float g_xs2[ROWS2 * DI];
__device__ __align__(16) float g_xc0[ROWS0 * DI];
__device__ __align__(16) float g_xc1[ROWS1 * DI];
__device__ __align__(16) float g_xc2[ROWS2 * DI];
__device__ __align__(16) float g_bssm[NSPLIT * ROWS_TOT * DSTATE];
__device__ __align__(16) float g_ys0[ROWS0 * DI];
__device__ __align__(16) float g_ys1[ROWS1 * DI];
__device__ __align__(16) float g_ys2[ROWS2 * DI];
__device__ __align__(16) float g_fused[ROWS_FULL * DI];
__device__ __align__(16) float g_ctx[ROWS_FULL * DI];
__device__ __align__(16) float g_h[ROWS_FULL * (DI / 2)];
__device__ __align__(16) float g_mmin[ROWS_FULL * DI];
__device__ __align__(16) float g_preln[ROWS_FULL * DIM];
// half2 (k-paired) weight copies: in_proj | cg_w1 | cg_w2 | out_proj
__device__ __align__(16) uint32_t g_wh[5242880];
__device__ float g_sw[NSCALES];

// ---------------- helpers ----------------
__device__ __forceinline__ float sigmoidf(float x) { return 1.f / (1.f + expf(-x)); }
__device__ __forceinline__ float siluf(float x)    { return x / (1.f + expf(-x)); }
__device__ __forceinline__ float softplusf(float x){ return x > 20.f ? x : log1pf(expf(x)); }

__device__ __forceinline__ uint32_t pack_h2(float lo, float hi) {
    __half2 h = __floats2half2_rn(lo, hi);
    return *(uint32_t*)&h;
}

__device__ __forceinline__ void mma_f16(float* c, const uint32_t* a, uint32_t b0, uint32_t b1) {
    asm volatile(
        "mma.sync.aligned.m16n8k16.row.col.f32.f16.f16.f32 "
        "{%0,%1,%2,%3}, {%4,%5,%6,%7}, {%8,%9}, {%0,%1,%2,%3};\n"
        : "+f"(c[0]), "+f"(c[1]), "+f"(c[2]), "+f"(c[3])
        : "r"(a[0]), "r"(a[1]), "r"(a[2]), "r"(a[3]), "r"(b0), "r"(b1));
}

// ---------------- softmax over 3 scale weights ----------------
__global__ void softmax3_kernel(const float* __restrict__ sw) {
    float a = sw[0], b = sw[1], c = sw[2];
    float m = fmaxf(a, fmaxf(b, c));
    float ea = expf(a - m), eb = expf(b - m), ec = expf(c - m);
    float inv = 1.f / (ea + eb + ec);
    g_sw[0] = ea * inv; g_sw[1] = eb * inv; g_sw[2] = ec * inv;
}

// ---------------- all-weights preconvert into g_wh (one launch) -------------
__global__ void cvt_all_kernel(const float* __restrict__ w0, const float* __restrict__ w1,
                               const float* __restrict__ w2, const float* __restrict__ w3,
                               uint32_t* __restrict__ out) {
    int i = blockIdx.x * blockDim.x + threadIdx.x;
    if (i >= 5242880) return;
    const float* src; int N, li;
    if (i < 2097152)      { src = w0; N = 4096; li = i; }
    else if (i < 3145728) { src = w1; N = 1024; li = i - 2097152; }
    else if (i < 4194304) { src = w2; N = 2048; li = i - 3145728; }
    else                  { src = w3; N = 1024; li = i - 4194304; }
    int p = li / N, n = li - p * N;
    float a = src[(size_t)(2 * p) * N + n];
    float b = src[(size_t)(2 * p + 1) * N + n];
    out[i] = pack_h2(a, b);
}

// ---------------- FP16 tensor-core GEMM with fused epilogues (R14 winner) ---
#define A_GRP 132
#define B_GRP 130

template<int EPI>
__global__ __launch_bounds__(256)
void tgemm_kernel(const float* __restrict__ A, const uint32_t* __restrict__ Bh,
                  float* __restrict__ C, int M, int N, int K,
                  const float* __restrict__ e1, const float* __restrict__ e2) {
    __shared__ __align__(16) uint32_t Asm[16 * A_GRP];
    __shared__ __align__(16) uint32_t Bsm[16 * B_GRP];

    const int tid  = threadIdx.x;
    const int warp = tid >> 5;
    const int lane = tid & 31;
    const int wm = warp >> 2;
    const int wn = warp & 3;
    const int g  = lane >> 2;
    const int tg = lane & 3;

    const int m0 = blockIdx.y * 128;
    const int n0 = blockIdx.x * 128;

    float acc[4][4][4];
#pragma unroll
    for (int i = 0; i < 4; i++)
#pragma unroll
        for (int j = 0; j < 4; j++)
#pragma unroll
            for (int q = 0; q < 4; q++) acc[i][j][q] = 0.f;

    float4 a_pre[4];
    uint4  b_pre[2];

#pragma unroll
    for (int it = 0; it < 4; it++) {
        int v = tid + it * 256;
        int r = v >> 3, c4 = (v & 7) * 4;
        a_pre[it] = *(const float4*)&A[(size_t)(m0 + r) * K + c4];
    }
#pragma unroll
    for (int it = 0; it < 2; it++) {
        int v = tid + it * 256;
        int prow = v >> 5, n4 = (v & 31) * 4;
        b_pre[it] = *(const uint4*)&Bh[(size_t)prow * N + n0 + n4];
    }

    for (int k0 = 0; k0 < K; k0 += 32) {
#pragma unroll
        for (int it = 0; it < 4; it++) {
            int v = tid + it * 256;
            int r = v >> 3, c4 = (v & 7) * 4;
            int mi = r >> 4, rr = r & 15;
            float va[4] = {a_pre[it].x, a_pre[it].y, a_pre[it].z, a_pre[it].w};
#pragma unroll
            for (int j = 0; j < 2; j++) {
                int c = c4 + 2 * j;
                int p = (c & 15) >> 1, kstep = c >> 4;
                int ls = (rr & 7) * 4 + (p & 3);
                int slot = (p >> 2) * 2 + (rr >> 3);
                Asm[(mi * 2 + kstep) * A_GRP + ls * 4 + slot] = pack_h2(va[2 * j], va[2 * j + 1]);
            }
        }
#pragma unroll
        for (int it = 0; it < 2; it++) {
            int v = tid + it * 256;
            int prow = v >> 5, n4 = (v & 31) * 4;
            int pp = prow & 7, kstep = prow >> 3;
            uint32_t vb[4] = {b_pre[it].x, b_pre[it].y, b_pre[it].z, b_pre[it].w};
#pragma unroll
            for (int j = 0; j < 4; j++) {
                int nn = n4 + j;
                int ni = nn >> 3, cc = nn & 7;
                int ls = cc * 4 + (pp & 3);
                int slot = pp >> 2;
                Bsm[ni * B_GRP + kstep * 64 + ls * 2 + slot] = vb[j];
            }
        }
        __syncthreads();

        if (k0 + 32 < K) {
#pragma unroll
            for (int it = 0; it < 4; it++) {
                int v = tid + it * 256;
                int r = v >> 3, c4 = (v & 7) * 4;
                a_pre[it] = *(const float4*)&A[(size_t)(m0 + r) * K + (k0 + 32) + c4];
            }
            int ph0 = (k0 + 32) >> 1;
#pragma unroll
            for (int it = 0; it < 2; it++) {
                int v = tid + it * 256;
                int prow = v >> 5, n4 = (v & 31) * 4;
                b_pre[it] = *(const uint4*)&Bh[(size_t)(ph0 + prow) * N + n0 + n4];
            }
        }

#pragma unroll
        for (int kstep = 0; kstep < 2; kstep++) {
            uint32_t bq[4][2];
#pragma unroll
            for (int nj = 0; nj < 4; nj++) {
                int ni_g = wn * 4 + nj;
                *(uint2*)bq[nj] = *(const uint2*)&Bsm[ni_g * B_GRP + kstep * 64 + lane * 2];
            }
            uint32_t af[4][4];
#pragma unroll
            for (int mi = 0; mi < 4; mi++) {
                int mi_g = wm * 4 + mi;
                *(uint4*)af[mi] = *(const uint4*)&Asm[(mi_g * 2 + kstep) * A_GRP + lane * 4];
            }
#pragma unroll
            for (int mi = 0; mi < 4; mi++)
#pragma unroll
                for (int nj = 0; nj < 4; nj++)
                    mma_f16(acc[mi][nj], af[mi], bq[nj][0], bq[nj][1]);
        }
        __syncthreads();
    }

#pragma unroll
    for (int mi = 0; mi < 4; mi++) {
#pragma unroll
        for (int ni = 0; ni < 4; ni++) {
            int r0 = m0 + wm * 64 + mi * 16 + g;
            int cb = n0 + wn * 32 + ni * 8 + tg * 2;
#pragma unroll
            for (int half = 0; half < 2; half++) {
                int row = r0 + half * 8;
                float v0 = acc[mi][ni][half * 2 + 0];
                float v1 = acc[mi][ni][half * 2 + 1];
                size_t idx = (size_t)row * N + cb;
                float o0, o1;
                if (EPI == 0) {
                    o0 = v0; o1 = v1;
                } else if (EPI == 1) {
                    o0 = siluf(v0); o1 = siluf(v1);
                } else if (EPI == 2) {
                    float g0 = e2[(size_t)row * (2 * DI) + cb];
                    float g1 = e2[(size_t)row * (2 * DI) + cb + 1];
                    o0 = e1[idx] * sigmoidf(v0) * siluf(g0);
                    o1 = e1[idx + 1] * sigmoidf(v1) * siluf(g1);
                } else {
                    o0 = v0 + e1[idx];
                    o1 = v1 + e1[idx + 1];
                }
                *(float2*)&C[idx] = make_float2(o0, o1);
            }
        }
    }
}

// ---------------- batched downsample s1+s2 (mean pool), float4 --------------
__global__ void ds_all_kernel(const float* __restrict__ xz,
                              float* __restrict__ xs1, float* __restrict__ xs2) {
    const int n1 = ROWS1 * (DI / 4);
    const int n2 = ROWS2 * (DI / 4);
    int idx = blockIdx.x * blockDim.x + threadIdx.x;
    if (idx >= n1 + n2) return;
    int stride, Ts, li;
    float* xs;
    if (idx < n1) { stride = 2; Ts = T_LEN / 2; li = idx; xs = xs1; }
    else          { stride = 4; Ts = T_LEN / 4; li = idx - n1; xs = xs2; }
    int c4 = (li & (DI / 4 - 1)) * 4;
    int rt = li / (DI / 4);
    int t = rt % Ts;
    int bb = rt / Ts;
    float4 acc = make_float4(0.f, 0.f, 0.f, 0.f);
    for (int r = 0; r < stride; r++) {
        float4 v = *(const float4*)&xz[(size_t)(bb * T_LEN + t * stride + r) * (2 * DI) + c4];
        acc.x += v.x; acc.y += v.y; acc.z += v.z; acc.w += v.w;
    }
    float inv = 1.f / (float)stride;
    acc.x *= inv; acc.y *= inv; acc.z *= inv; acc.w *= inv;
    *(float4*)&xs[(size_t)rt * DI + c4] = acc;
}

// ---------------- batched causal conv (K=4) + silu, all scales --------------
__global__ void conv_all_kernel(const float* __restrict__ xz,
                                const float* __restrict__ xs1, const float* __restrict__ xs2,
                                const float* __restrict__ conv_w, const float* __restrict__ conv_b,
                                float* __restrict__ xc0, float* __restrict__ xc1,
                                float* __restrict__ xc2) {
    int idx = blockIdx.x * blockDim.x + threadIdx.x;
    const int total = ROWS_TOT * (DI / 4);
    if (idx >= total) return;
    int c4 = (idx & (DI / 4 - 1)) * 4;
    int rt = idx / (DI / 4);
    int s, lrt, Ts, ld;
    const float* xin;
    float* xc;
    if (rt < ROWS0)              { s = 0; lrt = rt;              Ts = T_LEN;     xin = xz;  ld = 2 * DI; xc = xc0; }
    else if (rt < ROWS0 + ROWS1) { s = 1; lrt = rt - ROWS0;      Ts = T_LEN / 2; xin = xs1; ld = DI;     xc = xc1; }
    else                         { s = 2; lrt = rt - ROWS0 - ROWS1; Ts = T_LEN / 4; xin = xs2; ld = DI;  xc = xc2; }
    const float* w = conv_w + (size_t)s * DI * KCONV;
    const float* b = conv_b + (size_t)s * DI;
    int t = lrt % Ts;
    int bb = lrt / Ts;
    float4 w0 = *(const float4*)&w[(c4 + 0) * KCONV];
    float4 w1 = *(const float4*)&w[(c4 + 1) * KCONV];
    float4 w2 = *(const float4*)&w[(c4 + 2) * KCONV];
    float4 w3 = *(const float4*)&w[(c4 + 3) * KCONV];
    float4 acc = *(const float4*)&b[c4];
    const float wk[4][4] = {{w0.x, w0.y, w0.z, w0.w}, {w1.x, w1.y, w1.z, w1.w},
                            {w2.x, w2.y, w2.z, w2.w}, {w3.x, w3.y, w3.z, w3.w}};
#pragma unroll
    for (int k = 0; k < KCONV; k++) {
        int tt = t - (KCONV - 1) + k;
        if (tt >= 0) {
            float4 v = *(const float4*)&xin[(size_t)(bb * Ts + tt) * ld + c4];
            acc.x = fmaf(wk[0][k], v.x, acc.x);
            acc.y = fmaf(wk[1][k], v.y, acc.y);
            acc.z = fmaf(wk[2][k], v.z, acc.z);
            acc.w = fmaf(wk[3][k], v.w, acc.w);
        }
    }
    acc.x = siluf(acc.x); acc.y = siluf(acc.y);
    acc.z = siluf(acc.z); acc.w = siluf(acc.w);
    *(float4*)&xc[(size_t)lrt * DI + c4] = acc;
}

// ---------------- batched B_ssm partials, all scales ------------------------
#define BSSM_ROWS 256
#define XT_P 257

__global__ __launch_bounds__(256)
void bssm_all_kernel(const float* __restrict__ xc0, const float* __restrict__ xc1,
                     const float* __restrict__ xc2, const float* __restrict__ xproj_w,
                     float* __restrict__ bssm_p) {
    __shared__ float xt[32 * XT_P];
    __shared__ __align__(16) float ws[32 * 16];
    const int tid = threadIdx.x;
    int bx = blockIdx.x;
    int s, lb, rows, sbase;
    const float* xc;
    if (bx < 64)      { s = 0; lb = bx;      rows = ROWS0; sbase = SB0; xc = xc0; }
    else if (bx < 96) { s = 1; lb = bx - 64; rows = ROWS1; sbase = SB1; xc = xc1; }
    else              { s = 2; lb = bx - 96; rows = ROWS2; sbase = SB2; xc = xc2; }
    const float* xproj = xproj_w + (size_t)s * DI * 2 * DSTATE;
    const int row0 = lb * BSSM_ROWS;
    const int ks0 = blockIdx.y * (DI / NSPLIT);
    const int rg = tid >> 2;
    const int jq = tid & 3;
    float acc[4][4];
#pragma unroll
    for (int i = 0; i < 4; i++)
#pragma unroll
        for (int j = 0; j < 4; j++) acc[i][j] = 0.f;

    for (int k0 = ks0; k0 < ks0 + DI / NSPLIT; k0 += 32) {
#pragma unroll
        for (int i = 0; i < 8; i++) {
            int v = tid + i * 256;
            int lr = v >> 3, c4 = (v & 7) * 4;
            float4 xv = *(const float4*)&xc[(size_t)(row0 + lr) * DI + k0 + c4];
            xt[(c4 + 0) * XT_P + lr] = xv.x;
            xt[(c4 + 1) * XT_P + lr] = xv.y;
            xt[(c4 + 2) * XT_P + lr] = xv.z;
            xt[(c4 + 3) * XT_P + lr] = xv.w;
        }
        {
            int kk = tid >> 4, j = tid & 15;
#pragma unroll
            for (int i = 0; i < 2; i++)
                ws[(kk + i * 16) * 16 + j] = xproj[(size_t)(k0 + kk + i * 16) * (2 * DSTATE) + j];
        }
        __syncthreads();
#pragma unroll 8
        for (int kk = 0; kk < 32; kk++) {
            float4 w4 = *(const float4*)&ws[kk * 16 + jq * 4];
            float x0 = xt[kk * XT_P + rg * 4 + 0];
            float x1 = xt[kk * XT_P + rg * 4 + 1];
            float x2 = xt[kk * XT_P + rg * 4 + 2];
            float x3 = xt[kk * XT_P + rg * 4 + 3];
            acc[0][0] = fmaf(x0, w4.x, acc[0][0]); acc[0][1] = fmaf(x0, w4.y, acc[0][1]);
            acc[0][2] = fmaf(x0, w4.z, acc[0][2]); acc[0][3] = fmaf(x0, w4.w, acc[0][3]);
            acc[1][0] = fmaf(x1, w4.x, acc[1][0]); acc[1][1] = fmaf(x1, w4.y, acc[1][1]);
            acc[1][2] = fmaf(x1, w4.z, acc[1][2]); acc[1][3] = fmaf(x1, w4.w, acc[1][3]);
            acc[2][0] = fmaf(x2, w4.x, acc[2][0]); acc[2][1] = fmaf(x2, w4.y, acc[2][1]);
            acc[2][2] = fmaf(x2, w4.z, acc[2][2]); acc[2][3] = fmaf(x2, w4.w, acc[2][3]);
            acc[3][0] = fmaf(x3, w4.x, acc[3][0]); acc[3][1] = fmaf(x3, w4.y, acc[3][1]);
            acc[3][2] = fmaf(x3, w4.z, acc[3][2]); acc[3][3] = fmaf(x3, w4.w, acc[3][3]);
        }
        __syncthreads();
    }
#pragma unroll
    for (int i = 0; i < 4; i++) {
        size_t o = (size_t)sbase + ((size_t)blockIdx.y * rows + row0 + rg * 4 + i) * DSTATE + jq * 4;
        *(float4*)&bssm_p[o] = *(float4*)acc[i];
    }
}

// ---------------- batched SSM pointwise, all scales -------------------------
__global__ __launch_bounds__(256)
void ssm_all_kernel(const float* __restrict__ xc0, const float* __restrict__ xc1,
                    const float* __restrict__ xc2, const float* __restrict__ bssm_p,
                    const float* __restrict__ dtproj_w, const float* __restrict__ dtproj_b,
                    const float* __restrict__ D_param,
                    const float* __restrict__ xz,
                    const float* __restrict__ xs1, const float* __restrict__ xs2,
                    float* __restrict__ ys0, float* __restrict__ ys1,
                    float* __restrict__ ys2) {
    int bx = blockIdx.x;
    int s, r0, rows, sbase, ld;
    const float* xc;
    const float* xin;
    float* ys;
    if (bx < ROWS0 / 8) {
        s = 0; r0 = bx * 8; rows = ROWS0; sbase = SB0; xc = xc0; xin = xz; ld = 2 * DI; ys = ys0;
    } else if (bx < (ROWS0 + ROWS1) / 8) {
        s = 1; r0 = (bx - ROWS0 / 8) * 8; rows = ROWS1; sbase = SB1; xc = xc1; xin = xs1; ld = DI; ys = ys1;
    } else {
        s = 2; r0 = (bx - (ROWS0 + ROWS1) / 8) * 8; rows = ROWS2; sbase = SB2; xc = xc2; xin = xs2; ld = DI; ys = ys2;
    }
    const float* dtw = dtproj_w + (size_t)s * DSTATE * DI;
    const float* dtb = dtproj_b + (size_t)s * DI;
    const float* D   = D_param + (size_t)s * DI;
    const int c4 = blockIdx.y * 1024 + threadIdx.x * 4;

    float4 wv[DSTATE];
#pragma unroll
    for (int k = 0; k < DSTATE; k++)
        wv[k] = *(const float4*)&dtw[k * DI + c4];
    float4 dtb4 = *(const float4*)&dtb[c4];
    float4 D4   = *(const float4*)&D[c4];

    __shared__ float bs[8 * DSTATE];
    if (threadIdx.x < 8 * DSTATE) {
        int rr = threadIdx.x >> 4, k = threadIdx.x & 15;
        float v = 0.f;
#pragma unroll
        for (int sp = 0; sp < NSPLIT; sp++)
            v += bssm_p[(size_t)sbase + ((size_t)sp * rows + r0 + rr) * DSTATE + k];
        bs[rr * DSTATE + k] = v;
    }
    __syncthreads();

#pragma unroll
    for (int rr = 0; rr < 8; rr++) {
        int row = r0 + rr;
        float4 dt = dtb4;
#pragma unroll
        for (int k = 0; k < DSTATE; k++) {
            float bk = bs[rr * DSTATE + k];
            dt.x = fmaf(bk, wv[k].x, dt.x);
            dt.y = fmaf(bk, wv[k].y, dt.y);
            dt.z = fmaf(bk, wv[k].z, dt.z);
            dt.w = fmaf(bk, wv[k].w, dt.w);
        }
        float4 xcv = *(const float4*)&xc[(size_t)row * DI + c4];
        float4 xv  = *(const float4*)&xin[(size_t)row * ld + c4];
        float4 o;
        o.x = xcv.x * sigmoidf(softplusf(dt.x)) + D4.x * xv.x;
        o.y = xcv.y * sigmoidf(softplusf(dt.y)) + D4.y * xv.y;
        o.z = xcv.z * sigmoidf(softplusf(dt.z)) + D4.z * xv.z;
        o.w = xcv.w * sigmoidf(softplusf(dt.w)) + D4.w * xv.w;
        *(float4*)&ys[(size_t)row * DI + c4] = o;
    }
}

// ---------------- merged upsample + fuse (all 3 scales in one pass) ----------
__global__ void ups_fuse_kernel(const float* __restrict__ ys0,
                                const float* __restrict__ ys1,
                                const float* __restrict__ ys2,
                                float* __restrict__ fused, float* __restrict__ ctx) {
    int idx = blockIdx.x * blockDim.x + threadIdx.x;
    const int total4 = ROWS_FULL * (DI / 4);
    if (idx >= total4) return;
    int c4 = (idx & (DI / 4 - 1)) * 4;
    int rt = idx / (DI / 4);
    int t = rt % T_LEN;
    int bb = rt / T_LEN;

    float4 v0 = *(const float4*)&ys0[(size_t)(bb * T_LEN + t) * DI + c4];

    float4 v1, v2;
    {
        const int Ts = T_LEN / 2;
        float coord = (t + 0.5f) * 0.5f - 0.5f;
        coord = fminf(fmaxf(coord, 0.f), (float)(Ts - 1));
        int lo = (int)floorf(coord);
        int hi = min(lo + 1, Ts - 1);
        float wf = coord - (float)lo;
        float4 a = *(const float4*)&ys1[(size_t)(bb * Ts + lo) * DI + c4];
        float4 b = *(const float4*)&ys1[(size_t)(bb * Ts + hi) * DI + c4];
        v1.x = a.x + (b.x - a.x) * wf; v1.y = a.y + (b.y - a.y) * wf;
        v1.z = a.z + (b.z - a.z) * wf; v1.w = a.w + (b.w - a.w) * wf;
    }
    {
        const int Ts = T_LEN / 4;
        float coord = (t + 0.5f) * 0.25f - 0.5f;
        coord = fminf(fmaxf(coord, 0.f), (float)(Ts - 1));
        int lo = (int)floorf(coord);
        int hi = min(lo + 1, Ts - 1);
        float wf = coord - (float)lo;
        float4 a = *(const float4*)&ys2[(size_t)(bb * Ts + lo) * DI + c4];
        float4 b = *(const float4*)&ys2[(size_t)(bb * Ts + hi) * DI + c4];
        v2.x = a.x + (b.x - a.x) * wf; v2.y = a.y + (b.y - a.y) * wf;
        v2.z = a.z + (b.z - a.z) * wf; v2.w = a.w + (b.w - a.w) * wf;
    }

    float w0 = g_sw[0], w1 = g_sw[1], w2 = g_sw[2];
    float4 f, cx;
    f.x = w0 * v0.x + w1 * v1.x + w2 * v2.x;
    f.y = w0 * v0.y + w1 * v1.y + w2 * v2.y;
    f.z = w0 * v0.z + w1 * v1.z + w2 * v2.z;
    f.w = w0 * v0.w + w1 * v1.w + w2 * v2.w;
    const float third = 1.f / 3.f;
    cx.x = (v0.x + v1.x + v2.x) * third;
    cx.y = (v0.y + v1.y + v2.y) * third;
    cx.z = (v0.z + v1.z + v2.z) * third;
    cx.w = (v0.w + v1.w + v2.w) * third;

    size_t o = (size_t)rt * DI + c4;
    *(float4*)&fused[o] = f;
    *(float4*)&ctx[o] = cx;
}

// ---------------- LayerNorm over last dim (1024), float4 ----------------
__global__ __launch_bounds__(256)
void ln_kernel(const float* __restrict__ y, const float* __restrict__ g,
               const float* __restrict__ b, float* __restrict__ out) {
    int row = blockIdx.x;
    const float* yr = y + (size_t)row * DIM;
    int c4 = threadIdx.x * 4;
    float4 v = *(const float4*)&yr[c4];
    float s  = v.x + v.y + v.z + v.w;
    float s2 = v.x * v.x + v.y * v.y + v.z * v.z + v.w * v.w;
#pragma unroll
    for (int o = 16; o > 0; o >>= 1) {
        s  += __shfl_down_sync(0xffffffffu, s, o);
        s2 += __shfl_down_sync(0xffffffffu, s2, o);
    }
    __shared__ float shs[8], shs2[8];
    __shared__ float smu, srstd;
    int wid = threadIdx.x >> 5, lane = threadIdx.x & 31;
    if (lane == 0) { shs[wid] = s; shs2[wid] = s2; }
    __syncthreads();
    if (wid == 0) {
        s  = lane < 8 ? shs[lane]  : 0.f;
        s2 = lane < 8 ? shs2[lane] : 0.f;
#pragma unroll
        for (int o = 4; o > 0; o >>= 1) {
            s  += __shfl_down_sync(0xffffffffu, s, o);
            s2 += __shfl_down_sync(0xffffffffu, s2, o);
        }
        if (lane == 0) {
            float mu = s / DIM;
            float var = s2 / DIM - mu * mu;
            smu = mu;
            srstd = rsqrtf(var + LN_EPS);
        }
    }
    __syncthreads();
    float mu = smu, rstd = srstd;
    float4 gv = *(const float4*)&g[c4];
    float4 bv = *(const float4*)&b[c4];
    float4 o;
    o.x = (v.x - mu) * rstd * gv.x + bv.x;
    o.y = (v.y - mu) * rstd * gv.y + bv.y;
    o.z = (v.z - mu) * rstd * gv.z + bv.z;
    o.w = (v.w - mu) * rstd * gv.w + bv.w;
    *(float4*)&out[(size_t)row * DIM + c4] = o;
}

// ---------------- launch ----------------
extern "C" void kernel_launch(void* const* d_in, const int* in_sizes, int n_in,
                              void* d_out, int out_size) {
    const float* x        = (const float*)d_in[0];
    const float* in_proj  = (const float*)d_in[1];
    const float* conv_w   = (const float*)d_in[2];
    const float* conv_b   = (const float*)d_in[3];
    const float* xproj_w  = (const float*)d_in[4];
    const float* dtproj_w = (const float*)d_in[5];
    const float* dtproj_b = (const float*)d_in[6];
    const float* D_param  = (const float*)d_in[7];
    const float* scale_w  = (const float*)d_in[8];
    const float* cg_w1    = (const float*)d_in[9];
    const float* cg_w2    = (const float*)d_in[10];
    const float* out_proj = (const float*)d_in[11];
    const float* ln_g     = (const float*)d_in[12];
    const float* ln_b     = (const float*)d_in[13];
    float* out = (float*)d_out;

    float *p_xz, *p_xs1, *p_xs2, *p_xc0, *p_xc1, *p_xc2, *p_bssm,
          *p_ys0, *p_ys1, *p_ys2, *p_fused, *p_ctx, *p_h, *p_mmin, *p_preln;
    uint32_t* p_wh;
    cudaGetSymbolAddress((void**)&p_xz, g_xz);
    cudaGetSymbolAddress((void**)&p_xs1, g_xs1);
    cudaGetSymbolAddress((void**)&p_xs2, g_xs2);
    cudaGetSymbolAddress((void**)&p_xc0, g_xc0);
    cudaGetSymbolAddress((void**)&p_xc1, g_xc1);
    cudaGetSymbolAddress((void**)&p_xc2, g_xc2);
    cudaGetSymbolAddress((void**)&p_bssm, g_bssm);
    cudaGetSymbolAddress((void**)&p_ys0, g_ys0);
    cudaGetSymbolAddress((void**)&p_ys1, g_ys1);
    cudaGetSymbolAddress((void**)&p_ys2, g_ys2);
    cudaGetSymbolAddress((void**)&p_fused, g_fused);
    cudaGetSymbolAddress((void**)&p_ctx, g_ctx);
    cudaGetSymbolAddress((void**)&p_h, g_h);
    cudaGetSymbolAddress((void**)&p_mmin, g_mmin);
    cudaGetSymbolAddress((void**)&p_preln, g_preln);
    cudaGetSymbolAddress((void**)&p_wh, g_wh);

    uint32_t* p_w0h = p_wh;                                   // [512][4096]
    uint32_t* p_w1h = p_w0h + (size_t)(DIM / 2) * 2 * DI;     // [1024][1024]
    uint32_t* p_w2h = p_w1h + (size_t)(DI / 2) * (DI / 2);    // [512][2048]
    uint32_t* p_w3h = p_w2h + (size_t)(DI / 4) * DI;          // [1024][1024]

    softmax3_kernel<<<1, 1>>>(scale_w);

    // 0) preconvert all weights in one launch
    cvt_all_kernel<<<(5242880 + 255) / 256, 256>>>(in_proj, cg_w1, cg_w2, out_proj, p_wh);

    // 1) xz = x @ in_proj_w   (16384 x 4096, K=1024)
    {
        dim3 grid(2 * DI / 128, ROWS_FULL / 128);
        tgemm_kernel<0><<<grid, 256>>>(x, p_w0h, p_xz, ROWS_FULL, 2 * DI, DIM,
                                       nullptr, nullptr);
    }

    // 2) batched SSM path (all 3 scales per launch)
    {
        int nds = (ROWS1 + ROWS2) * (DI / 4);
        ds_all_kernel<<<(nds + 255) / 256, 256>>>(p_xz, p_xs1, p_xs2);

        int nconv = ROWS_TOT * (DI / 4);
        conv_all_kernel<<<(nconv + 255) / 256, 256>>>(p_xz, p_xs1, p_xs2,
                                                      conv_w, conv_b,
                                                      p_xc0, p_xc1, p_xc2);

        dim3 bgrid(ROWS_TOT / BSSM_ROWS, NSPLIT);   // (112, 8)
        bssm_all_kernel<<<bgrid, 256>>>(p_xc0, p_xc1, p_xc2, xproj_w, p_bssm);

        dim3 sgrid(ROWS_TOT / 8, DI / 1024);        // (3584, 2)
        ssm_all_kernel<<<sgrid, 256>>>(p_xc0, p_xc1, p_xc2, p_bssm,
                                       dtproj_w, dtproj_b, D_param,
                                       p_xz, p_xs1, p_xs2,
                                       p_ys0, p_ys1, p_ys2);
    }

    // 2b) merged upsample + fuse
    {
        int total4 = ROWS_FULL * (DI / 4);
        ups_fuse_kernel<<<(total4 + 255) / 256, 256>>>(p_ys0, p_ys1, p_ys2, p_fused, p_ctx);
    }

    // 3) h = silu(ctx @ cg_w1)   (16384 x 1024, K=2048)
    {
        dim3 grid((DI / 2) / 128, ROWS_FULL / 128);
        tgemm_kernel<1><<<grid, 256>>>(p_ctx, p_w1h, p_h, ROWS_FULL, DI / 2, DI,
                                       nullptr, nullptr);
    }
    // 4) mm_in = fused * sigmoid(h @ cg_w2) * silu(gate)  (16384 x 2048, K=1024)
    {
        dim3 grid(DI / 128, ROWS_FULL / 128);
        tgemm_kernel<2><<<grid, 256>>>(p_h, p_w2h, p_mmin, ROWS_FULL, DI, DI / 2,
                                       p_fused, p_xz + DI);
    }
    // 5) preln = mm_in @ out_proj + x   (16384 x 1024, K=2048)
    {
        dim3 grid(DIM / 128, ROWS_FULL / 128);
        tgemm_kernel<3><<<grid, 256>>>(p_mmin, p_w3h, p_preln, ROWS_FULL, DIM, DI,
                                       x, nullptr);
    }
    // 6) LayerNorm -> out
    ln_kernel<<<ROWS_FULL, 256>>>(p_preln, ln_g, ln_b, out);
}